// round 13
// baseline (speedup 1.0000x reference)
#include <cuda_runtime.h>
#include <cuda_fp16.h>
#include <cstdint>

#define F        512
#define SPLIT    16384
#define NLIL     2048
#define NLAYERS  8
#define NMLIL    8
#define MTOT     (SPLIT + NMLIL * NLIL)   /* 32768 */

#define BM   128
#define BN   128
#define KC   32
#define NCH  (F / KC)                     /* 16 chunks */

/* A tiles: fp16, stride 40 halves (80 B) per row -> 20 u32 words */
#define LDAH_W 20
#define A_TILE_BYTES (BM * 80)            /* 10240 */
/* B tile: raw fp32, stride 40 floats (160 B) per row */
#define LDB_F  40
#define B_TILE_BYTES (BN * 160)           /* 20480 */

#define OFF_AH 0
#define OFF_AL (A_TILE_BYTES)
#define OFF_B  (2 * A_TILE_BYTES)
#define STAGE_BYTES (2 * A_TILE_BYTES + B_TILE_BYTES)   /* 40960 */
#define SMEM_DYN (2 * STAGE_BYTES)                      /* 81920 -> 2 CTAs/SM */

__device__ float g_ping[(size_t)MTOT * F];
__device__ float g_pong[(size_t)MTOT * F];
__device__ float g_WT[(size_t)NLAYERS * F * F];

/* ---------------- helpers ---------------- */
__device__ __forceinline__ uint32_t smem_u32(const void* p) {
    uint32_t a;
    asm("{ .reg .u64 t; cvta.to.shared.u64 t, %1; cvt.u32.u64 %0, t; }" : "=r"(a) : "l"(p));
    return a;
}
__device__ __forceinline__ void cpasync16(uint32_t s, const void* g) {
    asm volatile("cp.async.cg.shared.global [%0], [%1], 16;" :: "r"(s), "l"(g) : "memory");
}
#define CP_COMMIT() asm volatile("cp.async.commit_group;" ::: "memory")
#define CP_WAIT0()  asm volatile("cp.async.wait_group 0;" ::: "memory")

/* split a float2 into packed fp16 hi + fp16 lo (each uint32 = half2) */
__device__ __forceinline__ void split_h2(float2 v, uint32_t& h, uint32_t& l) {
    __half2 hh = __float22half2_rn(v);
    float2 hf = __half22float2(hh);
    __half2 ll = __float22half2_rn(make_float2(v.x - hf.x, v.y - hf.y));
    h = *reinterpret_cast<uint32_t*>(&hh);
    l = *reinterpret_cast<uint32_t*>(&ll);
}
__device__ __forceinline__ void mma16(float* c, const uint32_t* a, uint32_t b0, uint32_t b1) {
    asm volatile(
        "mma.sync.aligned.m16n8k16.row.col.f32.f16.f16.f32 "
        "{%0,%1,%2,%3}, {%4,%5,%6,%7}, {%8,%9}, {%0,%1,%2,%3};"
        : "+f"(c[0]), "+f"(c[1]), "+f"(c[2]), "+f"(c[3])
        : "r"(a[0]), "r"(a[1]), "r"(a[2]), "r"(a[3]), "r"(b0), "r"(b1));
}

/* -------- Wbig transpose: WT[l][g][f] = W[l][f][g] (so B is [N,K]) -------- */
__global__ void transpose_wbig(const float* __restrict__ W, float* __restrict__ WT) {
    __shared__ float t[32][33];
    int l = blockIdx.z;
    int f0 = blockIdx.x * 32, g0 = blockIdx.y * 32;
    int x = threadIdx.x, y = threadIdx.y;
    const float* Wl = W + (size_t)l * F * F;
    float* WTl = WT + (size_t)l * F * F;
#pragma unroll
    for (int r = 0; r < 32; r += 8)
        t[y + r][x] = Wl[(size_t)(f0 + y + r) * F + g0 + x];
    __syncthreads();
#pragma unroll
    for (int r = 0; r < 32; r += 8)
        WTl[(size_t)(g0 + y + r) * F + f0 + x] = t[x][y + r];
}

/* ------------------------- per-layer GEMM ------------------------- */
__global__ __launch_bounds__(256, 2)
void layer_kernel(const float* __restrict__ src, float* __restrict__ dst,
                  const float* __restrict__ WT, const float* __restrict__ Bbig,
                  const float* __restrict__ Wlil, const float* __restrict__ Blil,
                  int layer)
{
    extern __shared__ char smemb[];
    const int tid  = threadIdx.x;
    const int warp = tid >> 5;
    const int lane = tid & 31;
    const int wm   = warp >> 2;         /* 0..1 : 64-row slab  */
    const int wn   = warp & 3;          /* 0..3 : 32-col slab  */
    const int row0 = blockIdx.x * BM;
    const int n0   = blockIdx.y * BN;

    const float* wsrc;
    const float* bias;
    if (row0 < SPLIT) {
        wsrc = WT + (size_t)layer * F * F + (size_t)n0 * F;
        bias = Bbig + layer * F + n0;
    } else {
        int mi = (row0 - SPLIT) / NLIL;
        wsrc = Wlil + (size_t)(layer * NMLIL + mi) * F * F + (size_t)n0 * F;
        bias = Blil + (layer * NMLIL + mi) * F + n0;
    }
    const float* asrc = src + (size_t)row0 * F;

    const uint32_t sb = smem_u32(smemb);

    /* --- staging coordinates: thread pair per row --- */
    const int srow = tid >> 1;                  /* 0..127 */
    const int sh   = tid & 1;                   /* half-row selector (16 floats) */
    const float* gA = asrc + (size_t)srow * F + sh * 16;
    const float* gB = wsrc + (size_t)srow * F + sh * 16;

    float4 pa[4];

    auto issueB = [&](int t) {                  /* cp.async raw fp32 B tile */
        const int k0 = t * KC;
        const uint32_t d = sb + (t & 1) * STAGE_BYTES + OFF_B + srow * 160 + sh * 64;
#pragma unroll
        for (int c = 0; c < 4; ++c)
            cpasync16(d + c * 16, gB + k0 + c * 4);
        CP_COMMIT();
    };
    auto ldgA = [&](int t) {
        const int k0 = t * KC;
#pragma unroll
        for (int c = 0; c < 4; ++c)
            pa[c] = *(const float4*)(gA + k0 + c * 4);
    };
    auto stsA = [&](int t) {                    /* split -> fp16 Ah/Al tiles */
        char* st = smemb + (t & 1) * STAGE_BYTES;
        uint32_t* AH = (uint32_t*)(st + OFF_AH);
        uint32_t* AL = (uint32_t*)(st + OFF_AL);
        const int wbase = srow * LDAH_W + sh * 8;
#pragma unroll
        for (int c = 0; c < 4; ++c) {
            uint32_t h0, l0, h1, l1;
            split_h2(make_float2(pa[c].x, pa[c].y), h0, l0);
            split_h2(make_float2(pa[c].z, pa[c].w), h1, l1);
            uint2 hv; hv.x = h0; hv.y = h1;
            uint2 lv; lv.x = l0; lv.y = l1;
            *(uint2*)(AH + wbase + c * 2) = hv;
            *(uint2*)(AL + wbase + c * 2) = lv;
        }
    };

    float acc[4][4][4];
#pragma unroll
    for (int i = 0; i < 4; ++i)
#pragma unroll
        for (int j = 0; j < 4; ++j) {
            acc[i][j][0] = 0.f; acc[i][j][1] = 0.f;
            acc[i][j][2] = 0.f; acc[i][j][3] = 0.f;
        }

    const int lr = lane >> 2;   /* 0..7 */
    const int lc = lane & 3;    /* 0..3 */

    /* prologue */
    issueB(0);
    ldgA(0);
    stsA(0);
    CP_WAIT0();
    __syncthreads();

    for (int t = 0; t < NCH; ++t) {
        if (t + 1 < NCH) { issueB(t + 1); ldgA(t + 1); }

        const char* st = smemb + (t & 1) * STAGE_BYTES;
        const uint32_t* AH = (const uint32_t*)(st + OFF_AH);
        const uint32_t* AL = (const uint32_t*)(st + OFF_AL);
        const float*    Bs = (const float*)(st + OFF_B);

#pragma unroll
        for (int s = 0; s < 2; ++s) {           /* two k16 steps per chunk */
            /* A fragments: pre-split fp16, one .b32 per element pair */
            uint32_t ah[4][4], al[4][4];
#pragma unroll
            for (int mt = 0; mt < 4; ++mt) {
                const int r0 = wm * 64 + mt * 16 + lr;
                const int i0 = r0 * LDAH_W + s * 8 + lc;
                const int i1 = i0 + 8 * LDAH_W;
                ah[mt][0] = AH[i0];     al[mt][0] = AL[i0];
                ah[mt][1] = AH[i1];     al[mt][1] = AL[i1];
                ah[mt][2] = AH[i0 + 4]; al[mt][2] = AL[i0 + 4];
                ah[mt][3] = AH[i1 + 4]; al[mt][3] = AL[i1 + 4];
            }
#pragma unroll
            for (int nt = 0; nt < 4; ++nt) {
                const int nr = wn * 32 + nt * 8 + lr;
                const int j0 = nr * LDB_F + s * 16 + 2 * lc;
                const float2 u0 = *(const float2*)&Bs[j0];
                const float2 u1 = *(const float2*)&Bs[j0 + 8];
                uint32_t bh0, bl0, bh1, bl1;
                split_h2(u0, bh0, bl0);
                split_h2(u1, bh1, bl1);
                /* term-outer, mt-inner: consecutive MMAs hit different accs */
#pragma unroll
                for (int mt = 0; mt < 4; ++mt) mma16(acc[mt][nt], ah[mt], bh0, bh1);
#pragma unroll
                for (int mt = 0; mt < 4; ++mt) mma16(acc[mt][nt], al[mt], bh0, bh1);
#pragma unroll
                for (int mt = 0; mt < 4; ++mt) mma16(acc[mt][nt], ah[mt], bl0, bl1);
            }
        }

        if (t + 1 < NCH) {
            stsA(t + 1);        /* other buffer: safe w.r.t. readers of t */
            CP_WAIT0();         /* B(t+1) landed */
        }
        __syncthreads();
    }

    /* ---------------- epilogue: bias + store ---------------- */
#pragma unroll
    for (int mt = 0; mt < 4; ++mt) {
        const int r = row0 + wm * 64 + mt * 16 + lr;
#pragma unroll
        for (int nt = 0; nt < 4; ++nt) {
            const int nloc = wn * 32 + nt * 8 + lc * 2;
            const float bx = bias[nloc];
            const float by = bias[nloc + 1];
            float2 o0, o1;
            o0.x = acc[mt][nt][0] + bx; o0.y = acc[mt][nt][1] + by;
            o1.x = acc[mt][nt][2] + bx; o1.y = acc[mt][nt][3] + by;
            *(float2*)(dst + (size_t)r * F + n0 + nloc)       = o0;
            *(float2*)(dst + (size_t)(r + 8) * F + n0 + nloc) = o1;
        }
    }
}

/* ------------------------------ host ------------------------------ */
extern "C" void kernel_launch(void* const* d_in, const int* in_sizes, int n_in,
                              void* d_out, int out_size)
{
    const float* x    = (const float*)d_in[0];
    const float* Wbig = (const float*)d_in[1];
    const float* Bbig = (const float*)d_in[2];
    const float* Wlil = (const float*)d_in[3];
    const float* Blil = (const float*)d_in[4];
    float* out = (float*)d_out;

    float *ping, *pong, *wt;
    cudaGetSymbolAddress((void**)&ping, g_ping);
    cudaGetSymbolAddress((void**)&pong, g_pong);
    cudaGetSymbolAddress((void**)&wt, g_WT);

    cudaFuncSetAttribute(layer_kernel,
                         cudaFuncAttributeMaxDynamicSharedMemorySize, SMEM_DYN);

    transpose_wbig<<<dim3(16, 16, 8), dim3(32, 8)>>>(Wbig, wt);

    dim3 grid(MTOT / BM, F / BN);   /* 256 x 4 */
    for (int l = 0; l < NLAYERS; ++l) {
        const float* s = (l == 0) ? x : ((l & 1) ? ping : pong);
        float* d = (l == NLAYERS - 1) ? out : ((l & 1) ? pong : ping);
        layer_kernel<<<grid, 256, SMEM_DYN>>>(s, d, wt, Bbig, Wlil, Blil, l);
    }
}

// round 15
// speedup vs baseline: 1.0127x; 1.0127x over previous
#include <cuda_runtime.h>
#include <cstdint>

#define F        512
#define SPLIT    16384
#define NLIL     2048
#define NLAYERS  8
#define NMLIL    8
#define MTOT     (SPLIT + NMLIL * NLIL)   /* 32768 */

#define BM   128
#define BN   128
#define KC   16
#define NCH  (F / KC)                     /* 32 chunks */

#define LDSW 20                           /* floats per smem row (16 + pad 4) */
#define TILE_BYTES (BM * LDSW * 4)        /* 10240 */
#define OFF_AH 0
#define OFF_AL (TILE_BYTES)
#define OFF_BH (2 * TILE_BYTES)
#define OFF_BL (3 * TILE_BYTES)
#define STAGE_BYTES (4 * TILE_BYTES)      /* 40960 */
#define SMEM_DYN (2 * STAGE_BYTES)        /* 81920 -> 2 CTAs/SM */

/* split activations ping-pong (tf32-valued floats) */
__device__ float g_h0[(size_t)MTOT * F];
__device__ float g_l0[(size_t)MTOT * F];
__device__ float g_h1[(size_t)MTOT * F];
__device__ float g_l1[(size_t)MTOT * F];
/* split weights: big (transposed to [g][f]) and little (already [g][f]) */
__device__ float g_WTh[(size_t)NLAYERS * F * F];
__device__ float g_WTl[(size_t)NLAYERS * F * F];
__device__ float g_Wlh[(size_t)NLAYERS * NMLIL * F * F];
__device__ float g_Wll[(size_t)NLAYERS * NMLIL * F * F];

/* ---------------- helpers ---------------- */
__device__ __forceinline__ uint32_t smem_u32(const void* p) {
    uint32_t a;
    asm("{ .reg .u64 t; cvta.to.shared.u64 t, %1; cvt.u32.u64 %0, t; }" : "=r"(a) : "l"(p));
    return a;
}
__device__ __forceinline__ void cpasync16(uint32_t s, const void* g) {
    asm volatile("cp.async.cg.shared.global [%0], [%1], 16;" :: "r"(s), "l"(g) : "memory");
}
#define CP_COMMIT() asm volatile("cp.async.commit_group;" ::: "memory")
#define CP_WAIT0()  asm volatile("cp.async.wait_group 0;" ::: "memory")
#define CP_WAIT1()  asm volatile("cp.async.wait_group 1;" ::: "memory")

__device__ __forceinline__ float tf32_rna(float v) {
    uint32_t h;
    asm("cvt.rna.tf32.f32 %0, %1;" : "=r"(h) : "f"(v));
    return __uint_as_float(h);
}
__device__ __forceinline__ void mma8(float* c, const uint32_t* a, uint32_t b0, uint32_t b1) {
    asm volatile(
        "mma.sync.aligned.m16n8k8.row.col.f32.tf32.tf32.f32 "
        "{%0,%1,%2,%3}, {%4,%5,%6,%7}, {%8,%9}, {%0,%1,%2,%3};"
        : "+f"(c[0]), "+f"(c[1]), "+f"(c[2]), "+f"(c[3])
        : "r"(a[0]), "r"(a[1]), "r"(a[2]), "r"(a[3]), "r"(b0), "r"(b1));
}

/* -------- prep: elementwise split (x, Wlil) -------- */
__global__ void split_plain(const float* __restrict__ in,
                            float* __restrict__ oh, float* __restrict__ ol, int n4)
{
    int i = blockIdx.x * blockDim.x + threadIdx.x;
    if (i >= n4) return;
    float4 v = ((const float4*)in)[i];
    float4 h, l;
    h.x = tf32_rna(v.x); l.x = tf32_rna(v.x - h.x);
    h.y = tf32_rna(v.y); l.y = tf32_rna(v.y - h.y);
    h.z = tf32_rna(v.z); l.z = tf32_rna(v.z - h.z);
    h.w = tf32_rna(v.w); l.w = tf32_rna(v.w - h.w);
    ((float4*)oh)[i] = h;
    ((float4*)ol)[i] = l;
}

/* -------- prep: Wbig transpose + split: WT*[l][g][f] from W[l][f][g] -------- */
__global__ void split_wbig_T(const float* __restrict__ W,
                             float* __restrict__ WTh, float* __restrict__ WTl)
{
    __shared__ float t[32][33];
    int l = blockIdx.z;
    int f0 = blockIdx.x * 32, g0 = blockIdx.y * 32;
    int x = threadIdx.x, y = threadIdx.y;
    const float* Wl = W + (size_t)l * F * F;
    float* Oh = WTh + (size_t)l * F * F;
    float* Ol = WTl + (size_t)l * F * F;
#pragma unroll
    for (int r = 0; r < 32; r += 8)
        t[y + r][x] = Wl[(size_t)(f0 + y + r) * F + g0 + x];
    __syncthreads();
#pragma unroll
    for (int r = 0; r < 32; r += 8) {
        float v = t[x][y + r];
        float h = tf32_rna(v);
        Oh[(size_t)(g0 + y + r) * F + f0 + x] = h;
        Ol[(size_t)(g0 + y + r) * F + f0 + x] = tf32_rna(v - h);
    }
}

/* ------------------------- per-layer GEMM ------------------------- */
__global__ __launch_bounds__(256, 2)
void layer_kernel(const float* __restrict__ ah_src, const float* __restrict__ al_src,
                  float* __restrict__ dsth, float* __restrict__ dstl,
                  float* __restrict__ dstF,
                  const float* __restrict__ WTh, const float* __restrict__ WTl,
                  const float* __restrict__ Wlh, const float* __restrict__ Wll,
                  const float* __restrict__ Bbig, const float* __restrict__ Blil,
                  int layer)
{
    extern __shared__ char smemb[];
    const int tid  = threadIdx.x;
    const int warp = tid >> 5;
    const int lane = tid & 31;
    const int wm   = warp >> 2;         /* 0..1 : 64-row slab  */
    const int wn   = warp & 3;          /* 0..3 : 32-col slab  */
    const int row0 = blockIdx.x * BM;
    const int n0   = blockIdx.y * BN;

    const float *bh_src, *bl_src, *bias;
    if (row0 < SPLIT) {
        const size_t o = (size_t)layer * F * F + (size_t)n0 * F;
        bh_src = WTh + o;  bl_src = WTl + o;
        bias = Bbig + layer * F + n0;
    } else {
        int mi = (row0 - SPLIT) / NLIL;
        const size_t o = (size_t)(layer * NMLIL + mi) * F * F + (size_t)n0 * F;
        bh_src = Wlh + o;  bl_src = Wll + o;
        bias = Blil + (layer * NMLIL + mi) * F + n0;
    }
    const float* gah = ah_src + (size_t)row0 * F;
    const float* gal = al_src + (size_t)row0 * F;

    const uint32_t sb = smem_u32(smemb);

    /* --- cp.async staging: thread pair per row; 2x16B per tile --- */
    const int srow = tid >> 1;                  /* 0..127 */
    const int sh   = tid & 1;                   /* 8-float half of 16-float row */
    const size_t gofs = (size_t)srow * F + sh * 8;
    const uint32_t dofs = srow * (LDSW * 4) + sh * 32;

    auto issue = [&](int t) {
        const int k0 = t * KC;
        const uint32_t d = sb + (t & 1) * STAGE_BYTES + dofs;
        cpasync16(d + OFF_AH,      gah + gofs + k0);
        cpasync16(d + OFF_AH + 16, gah + gofs + k0 + 4);
        cpasync16(d + OFF_AL,      gal + gofs + k0);
        cpasync16(d + OFF_AL + 16, gal + gofs + k0 + 4);
        cpasync16(d + OFF_BH,      bh_src + gofs + k0);
        cpasync16(d + OFF_BH + 16, bh_src + gofs + k0 + 4);
        cpasync16(d + OFF_BL,      bl_src + gofs + k0);
        cpasync16(d + OFF_BL + 16, bl_src + gofs + k0 + 4);
        CP_COMMIT();
    };

    float acc[4][4][4];
#pragma unroll
    for (int i = 0; i < 4; ++i)
#pragma unroll
        for (int j = 0; j < 4; ++j) {
            acc[i][j][0] = 0.f; acc[i][j][1] = 0.f;
            acc[i][j][2] = 0.f; acc[i][j][3] = 0.f;
        }

    const int lr = lane >> 2;   /* 0..7 */
    const int lc = lane & 3;    /* 0..3 */

    issue(0);

    for (int t = 0; t < NCH; ++t) {
        if (t + 1 < NCH) { issue(t + 1); CP_WAIT1(); }
        else             { CP_WAIT0(); }
        __syncthreads();

        const uint32_t* st = (const uint32_t*)(smemb + (t & 1) * STAGE_BYTES);
        const uint32_t* AsH = st + OFF_AH / 4;
        const uint32_t* AsL = st + OFF_AL / 4;
        const uint32_t* BsH = st + OFF_BH / 4;
        const uint32_t* BsL = st + OFF_BL / 4;

#pragma unroll
        for (int s = 0; s < 2; ++s) {           /* two k8 steps per chunk */
            const int kb = s * 8;
            uint32_t ah[4][4], al[4][4];
#pragma unroll
            for (int mt = 0; mt < 4; ++mt) {
                const int r0 = wm * 64 + mt * 16 + lr;
                const int i0 = r0 * LDSW + kb + lc;
                const int i1 = i0 + 8 * LDSW;
                ah[mt][0] = AsH[i0];     al[mt][0] = AsL[i0];
                ah[mt][1] = AsH[i1];     al[mt][1] = AsL[i1];
                ah[mt][2] = AsH[i0 + 4]; al[mt][2] = AsL[i0 + 4];
                ah[mt][3] = AsH[i1 + 4]; al[mt][3] = AsL[i1 + 4];
            }
#pragma unroll
            for (int nt = 0; nt < 4; ++nt) {
                const int nr = wn * 32 + nt * 8 + lr;
                const int j0 = nr * LDSW + kb + lc;
                const uint32_t bh0 = BsH[j0], bh1 = BsH[j0 + 4];
                const uint32_t bl0 = BsL[j0], bl1 = BsL[j0 + 4];
                /* term-outer, mt-inner: consecutive MMAs hit different accs */
#pragma unroll
                for (int mt = 0; mt < 4; ++mt) mma8(acc[mt][nt], ah[mt], bh0, bh1);
#pragma unroll
                for (int mt = 0; mt < 4; ++mt) mma8(acc[mt][nt], al[mt], bh0, bh1);
#pragma unroll
                for (int mt = 0; mt < 4; ++mt) mma8(acc[mt][nt], ah[mt], bl0, bl1);
            }
        }
        __syncthreads();   /* all reads of buf t done before issue(t+2) overwrites */
    }

    /* ---------------- epilogue: bias + store (split for next layer) ---------------- */
    const bool last = (layer == NLAYERS - 1);
#pragma unroll
    for (int mt = 0; mt < 4; ++mt) {
        const int r = row0 + wm * 64 + mt * 16 + lr;
#pragma unroll
        for (int nt = 0; nt < 4; ++nt) {
            const int nloc = wn * 32 + nt * 8 + lc * 2;
            const float bx = bias[nloc];
            const float by = bias[nloc + 1];
            float y00 = acc[mt][nt][0] + bx, y01 = acc[mt][nt][1] + by;
            float y10 = acc[mt][nt][2] + bx, y11 = acc[mt][nt][3] + by;
            const size_t o0 = (size_t)r * F + n0 + nloc;
            const size_t o1 = (size_t)(r + 8) * F + n0 + nloc;
            if (last) {
                *(float2*)(dstF + o0) = make_float2(y00, y01);
                *(float2*)(dstF + o1) = make_float2(y10, y11);
            } else {
                float h00 = tf32_rna(y00), h01 = tf32_rna(y01);
                float h10 = tf32_rna(y10), h11 = tf32_rna(y11);
                *(float2*)(dsth + o0) = make_float2(h00, h01);
                *(float2*)(dsth + o1) = make_float2(h10, h11);
                *(float2*)(dstl + o0) = make_float2(tf32_rna(y00 - h00), tf32_rna(y01 - h01));
                *(float2*)(dstl + o1) = make_float2(tf32_rna(y10 - h10), tf32_rna(y11 - h11));
            }
        }
    }
}

/* ------------------------------ host ------------------------------ */
extern "C" void kernel_launch(void* const* d_in, const int* in_sizes, int n_in,
                              void* d_out, int out_size)
{
    const float* x    = (const float*)d_in[0];
    const float* Wbig = (const float*)d_in[1];
    const float* Bbig = (const float*)d_in[2];
    const float* Wlil = (const float*)d_in[3];
    const float* Blil = (const float*)d_in[4];
    float* out = (float*)d_out;

    float *h0, *l0, *h1, *l1, *wth, *wtl, *wlh, *wll;
    cudaGetSymbolAddress((void**)&h0, g_h0);
    cudaGetSymbolAddress((void**)&l0, g_l0);
    cudaGetSymbolAddress((void**)&h1, g_h1);
    cudaGetSymbolAddress((void**)&l1, g_l1);
    cudaGetSymbolAddress((void**)&wth, g_WTh);
    cudaGetSymbolAddress((void**)&wtl, g_WTl);
    cudaGetSymbolAddress((void**)&wlh, g_Wlh);
    cudaGetSymbolAddress((void**)&wll, g_Wll);

    cudaFuncSetAttribute(layer_kernel,
                         cudaFuncAttributeMaxDynamicSharedMemorySize, SMEM_DYN);

    /* prep: split weights + layer-0 activations */
    split_wbig_T<<<dim3(16, 16, 8), dim3(32, 8)>>>(Wbig, wth, wtl);
    {
        int n4 = (NLAYERS * NMLIL * F * F) / 4;
        split_plain<<<(n4 + 255) / 256, 256>>>(Wlil, wlh, wll, n4);
    }
    {
        int n4 = (MTOT * F) / 4;
        split_plain<<<(n4 + 255) / 256, 256>>>(x, h0, l0, n4);
    }

    dim3 grid(MTOT / BM, F / BN);   /* 256 x 4 */
    for (int l = 0; l < NLAYERS; ++l) {
        const float* ah = (l & 1) ? h1 : h0;
        const float* al = (l & 1) ? l1 : l0;
        float* dh = (l & 1) ? h0 : h1;
        float* dl = (l & 1) ? l0 : l1;
        layer_kernel<<<grid, 256, SMEM_DYN>>>(ah, al, dh, dl, out,
                                              wth, wtl, wlh, wll, Bbig, Blil, l);
    }
}